// round 15
// baseline (speedup 1.0000x reference)
#include <cuda_runtime.h>
#include <cstdint>

#define NCLS 21
#define NB 8
#define HW (512*512)
#define TPB 256
#define PXT 2
#define ITERS 1
#define PPB (TPB*PXT*ITERS)           // 512 pixels per block
#define BLOCKS_PER_IMG (HW/PPB)       // 512
#define NBLK (NB*BLOCKS_PER_IMG)      // 4096 -> ~7 waves: tiny tail
#define EPS 1e-10f

// Tiny global accumulators. Invariant: all-zero at the start of every launch.
// (Zero at module load; the elected last block re-zeroes after reading.)
__device__ float    g_I [NB][NCLS];
__device__ float    g_At[NB][NCLS];
__device__ float    g_Ao[NB][NCLS];
__device__ float    g_T [NB][NCLS];
__device__ unsigned g_done;

// Monotonic float->uint key with the class index packed in the low 5 bits.
// max() over these keys == argmax over the floats (ties -> larger k; negligible).
__device__ __forceinline__ unsigned fkey(float v, int k) {
    const unsigned b = __float_as_uint(v);
    const unsigned s = (unsigned)((int)b >> 31) | 0x80000000u;
    return ((b ^ s) & 0xFFFFFFE0u) | (unsigned)k;
}

__global__ __launch_bounds__(TPB, 4) void fused_kernel(const float* __restrict__ pr,
                                                       const int*   __restrict__ gt,
                                                       float*       __restrict__ out) {
    __shared__ float s_T [8][NCLS];   // warp-private logp sums
    __shared__ float c_I [8][NCLS];
    __shared__ float c_At[8][NCLS];
    __shared__ float c_Ao[8][NCLS];
    __shared__ int   s_last;
    __shared__ float sh_d[NB][NCLS], sh_N[NB][NCLS], sh_Ts[NB][NCLS];

    const int tid  = threadIdx.x;
    const int wid  = tid >> 5;
    const int lane = tid & 31;

    if (lane < NCLS) s_T[wid][lane] = 0.f;
    __syncwarp();

    // Per-lane radix-combine constants: bit set -> 0 (keep), clear -> ~0 (invert).
    const unsigned e0 = ((lane >> 0) & 1u) - 1u;
    const unsigned e1 = ((lane >> 1) & 1u) - 1u;
    const unsigned e2 = ((lane >> 2) & 1u) - 1u;
    const unsigned e3 = ((lane >> 3) & 1u) - 1u;
    const unsigned e4 = ((lane >> 4) & 1u) - 1u;

    const int b     = blockIdx.x / BLOCKS_PER_IMG;
    const int chunk = blockIdx.x % BLOCKS_PER_IMG;
    const float* __restrict__ base  = pr + (size_t)b * NCLS * HW;
    const int*   __restrict__ gbase = gt + (size_t)b * HW;

    // Lane k (<21) owns class k: atgt [0:10) | inter [10:20) | aout [20:30).
    // Max 64 px per warp -> each field < 1024.
    uint32_t acc = 0;

    #pragma unroll 1
    for (int it = 0; it < ITERS; ++it) {
        const int pix0 = chunk * PPB + it * (TPB * PXT) + tid * PXT;
        const int2 g2 = *(const int2*)(gbase + pix0);
        const float2* __restrict__ p = (const float2*)(base + pix0);

        // Gather the gt-class logit per pixel up front (L2 hits on streamed lines).
        float2 vgt;
        vgt.x = base[(size_t)g2.x * HW + pix0 + 0];
        vgt.y = base[(size_t)g2.y * HW + pix0 + 1];

        // Split accumulators: two independent chains per pixel component.
        float2 sa = make_float2(0.f, 0.f);
        float2 sb = make_float2(0.f, 0.f);
        uint2  ka = make_uint2(0u, 0u);   // IMNMX fold (even k)
        uint2  kb = make_uint2(0u, 0u);   // IMNMX fold (odd k)

        #pragma unroll
        for (int k = 0; k < NCLS; ++k) {
            const float2 v = p[(size_t)k * (HW / 2)];
            if (k & 1) {
                sb.x += __expf(v.x);  sb.y += __expf(v.y);
                kb.x = max(kb.x, fkey(v.x, k));  kb.y = max(kb.y, fkey(v.y, k));
            } else {
                sa.x += __expf(v.x);  sa.y += __expf(v.y);
                ka.x = max(ka.x, fkey(v.x, k));  ka.y = max(ka.y, fkey(v.y, k));
            }
        }
        const float2 se = make_float2(sa.x + sb.x, sa.y + sb.y);
        int2 am;
        am.x = (int)(max(ka.x, kb.x) & 31u);
        am.y = (int)(max(ka.y, kb.y) & 31u);

        // Radix-ballot histogram: 10 ballots reconstruct all 21 class masks.
        // inter = popc(mg & mp): gt==k AND pred==k.
        #define SLOT(G, AM, VGT, SE) do {                                          \
            const int      _g  = (G);                                              \
            const int      _a  = (AM);                                             \
            const unsigned gb0 = __ballot_sync(0xffffffffu, (_g)      & 1);        \
            const unsigned gb1 = __ballot_sync(0xffffffffu, (_g >> 1) & 1);        \
            const unsigned gb2 = __ballot_sync(0xffffffffu, (_g >> 2) & 1);        \
            const unsigned gb3 = __ballot_sync(0xffffffffu, (_g >> 3) & 1);        \
            const unsigned gb4 = __ballot_sync(0xffffffffu, (_g >> 4) & 1);        \
            const unsigned ab0 = __ballot_sync(0xffffffffu, (_a)      & 1);        \
            const unsigned ab1 = __ballot_sync(0xffffffffu, (_a >> 1) & 1);        \
            const unsigned ab2 = __ballot_sync(0xffffffffu, (_a >> 2) & 1);        \
            const unsigned ab3 = __ballot_sync(0xffffffffu, (_a >> 3) & 1);        \
            const unsigned ab4 = __ballot_sync(0xffffffffu, (_a >> 4) & 1);        \
            const unsigned mg = (gb0^e0) & (gb1^e1) & (gb2^e2) & (gb3^e3) & (gb4^e4); \
            const unsigned mp = (ab0^e0) & (ab1^e1) & (ab2^e2) & (ab3^e3) & (ab4^e4); \
            acc += (unsigned)__popc(mg)                                            \
                 + ((unsigned)__popc(mg & mp) << 10)                               \
                 + ((unsigned)__popc(mp) << 20);                                   \
            atomicAdd(&s_T[wid][_g], (VGT) - __logf(SE));                          \
        } while (0)

        SLOT(g2.x, am.x, vgt.x, se.x);
        SLOT(g2.y, am.y, vgt.y, se.y);
        #undef SLOT
    }

    if (lane < NCLS) {
        c_At[wid][lane] = (float)( acc         & 1023u);
        c_I [wid][lane] = (float)((acc >> 10)  & 1023u);
        c_Ao[wid][lane] = (float)( acc >> 20);
    }
    __syncthreads();

    if (tid < NCLS) {
        float I = 0.f, At = 0.f, Ao = 0.f, T = 0.f;
        #pragma unroll
        for (int w = 0; w < 8; ++w) {
            I += c_I[w][tid]; At += c_At[w][tid]; Ao += c_Ao[w][tid]; T += s_T[w][tid];
        }
        atomicAdd(&g_I [b][tid], I);
        atomicAdd(&g_At[b][tid], At);
        atomicAdd(&g_Ao[b][tid], Ao);
        atomicAdd(&g_T [b][tid], T);
    }

    // Elect the last block to finalize.
    __threadfence();
    __syncthreads();
    if (tid == 0) {
        const unsigned r = atomicAdd(&g_done, 1u);
        s_last = (r == NBLK - 1u) ? 1 : 0;
    }
    __syncthreads();
    if (!s_last) return;
    __threadfence();   // acquire: all other blocks' g_* writes are visible

    // ---- finalize (runs in exactly one block) ----
    if (tid < NB * NCLS) {
        const int bb = tid / NCLS, k = tid % NCLS;
        const float I  = g_I [bb][k];
        const float At = g_At[bb][k];
        const float Ao = g_Ao[bb][k];
        const float T  = g_T [bb][k];
        // Restore the all-zero invariant for the next launch/replay.
        g_I [bb][k] = 0.f; g_At[bb][k] = 0.f; g_Ao[bb][k] = 0.f; g_T[bb][k] = 0.f;
        sh_d [bb][k] = 2.f * I / (Ao + At + EPS);  // union + inter == a_out + a_tgt
        sh_N [bb][k] = At;
        sh_Ts[bb][k] = T;
    }
    if (tid == 0) g_done = 0u;
    __syncthreads();

    float w = 0.f, wT = 0.f, wN = 0.f;
    if (tid < NCLS) {
        float dice = 0.f, N = 0.f, T = 0.f;
        #pragma unroll
        for (int bb = 0; bb < NB; ++bb) {
            dice += sh_d[bb][tid];
            N    += sh_N[bb][tid];
            T    += sh_Ts[bb][tid];
        }
        w  = 1.f - dice * 0.125f;   // weight[k]
        wT = w * T;
        wN = w * N;
    }
    if (tid < 32) {
        #pragma unroll
        for (int o = 16; o > 0; o >>= 1) {
            w  += __shfl_down_sync(0xffffffffu, w,  o);
            wT += __shfl_down_sync(0xffffffffu, wT, o);
            wN += __shfl_down_sync(0xffffffffu, wN, o);
        }
        if (tid == 0) out[0] = w * (1.f / 21.f) - wT / wN;  // mean(weight) + celoss
    }
}

extern "C" void kernel_launch(void* const* d_in, const int* in_sizes, int n_in,
                              void* d_out, int out_size) {
    const float* pr;
    const int*   gt;
    if (in_sizes[0] > in_sizes[1]) {
        pr = (const float*)d_in[0];
        gt = (const int*)  d_in[1];
    } else {
        pr = (const float*)d_in[1];
        gt = (const int*)  d_in[0];
    }
    float* out = (float*)d_out;

    fused_kernel<<<NBLK, TPB>>>(pr, gt, out);
}

// round 16
// speedup vs baseline: 1.1530x; 1.1530x over previous
#include <cuda_runtime.h>
#include <cstdint>

#define NCLS 21
#define NB 8
#define HW (512*512)
#define TPB 256
#define PXT 4
#define ITERS 2
#define PPB (TPB*PXT*ITERS)           // 2048 pixels per block
#define BLOCKS_PER_IMG (HW/PPB)       // 128
#define NBLK (NB*BLOCKS_PER_IMG)      // 1024
#define EPS 1e-10f

// Tiny global accumulators. Invariant: all-zero at the start of every launch.
// (Zero at module load; the elected last block re-zeroes after reading.)
__device__ float    g_I [NB][NCLS];
__device__ float    g_At[NB][NCLS];
__device__ float    g_Ao[NB][NCLS];
__device__ float    g_T [NB][NCLS];
__device__ unsigned g_done;

// Pack class k into the low 5 mantissa bits of v (one LOP3). fmaxf over the
// packed floats == argmax over v (ties only on 27-bit-equal values; negligible).
__device__ __forceinline__ float fpack(float v, int k) {
    return __uint_as_float((__float_as_uint(v) & 0xFFFFFFE0u) | (unsigned)k);
}
#define FPACK_INIT __uint_as_float(0xFF7FFFE0u)   // -FLT_MAX, low bits clear

__global__ __launch_bounds__(TPB, 4) void fused_kernel(const float* __restrict__ pr,
                                                       const int*   __restrict__ gt,
                                                       float*       __restrict__ out) {
    __shared__ float s_T [8][NCLS];   // warp-private logp sums
    __shared__ float c_I [8][NCLS];
    __shared__ float c_At[8][NCLS];
    __shared__ float c_Ao[8][NCLS];
    __shared__ int   s_last;
    __shared__ float sh_d[NB][NCLS], sh_N[NB][NCLS], sh_Ts[NB][NCLS];

    const int tid  = threadIdx.x;
    const int wid  = tid >> 5;
    const int lane = tid & 31;

    if (lane < NCLS) s_T[wid][lane] = 0.f;
    __syncwarp();

    // Per-lane radix-combine constants: bit set -> 0 (keep), clear -> ~0 (invert).
    const unsigned e0 = ((lane >> 0) & 1u) - 1u;
    const unsigned e1 = ((lane >> 1) & 1u) - 1u;
    const unsigned e2 = ((lane >> 2) & 1u) - 1u;
    const unsigned e3 = ((lane >> 3) & 1u) - 1u;
    const unsigned e4 = ((lane >> 4) & 1u) - 1u;

    const int b     = blockIdx.x / BLOCKS_PER_IMG;
    const int chunk = blockIdx.x % BLOCKS_PER_IMG;
    const float* __restrict__ base  = pr + (size_t)b * NCLS * HW;
    const int*   __restrict__ gbase = gt + (size_t)b * HW;

    // Lane k (<21) owns class k: atgt [0:10) | inter [10:20) | aout [20:30).
    uint32_t acc = 0;

    #pragma unroll 1
    for (int it = 0; it < ITERS; ++it) {
        const int pix0 = chunk * PPB + it * (TPB * PXT) + tid * PXT;
        const int4 g4 = *(const int4*)(gbase + pix0);
        const float4* __restrict__ p = (const float4*)(base + pix0);

        // Gather the gt-class logit per pixel up front (L2 hits on streamed lines).
        float4 vgt;
        vgt.x = base[(size_t)g4.x * HW + pix0 + 0];
        vgt.y = base[(size_t)g4.y * HW + pix0 + 1];
        vgt.z = base[(size_t)g4.z * HW + pix0 + 2];
        vgt.w = base[(size_t)g4.w * HW + pix0 + 3];

        float4 se = make_float4(0.f, 0.f, 0.f, 0.f);
        float4 m  = make_float4(FPACK_INIT, FPACK_INIT, FPACK_INIT, FPACK_INIT);

        #pragma unroll
        for (int k = 0; k < NCLS; ++k) {
            const float4 v = p[(size_t)k * (HW / 4)];
            se.x += __expf(v.x);  se.y += __expf(v.y);
            se.z += __expf(v.z);  se.w += __expf(v.w);
            m.x = fmaxf(m.x, fpack(v.x, k));
            m.y = fmaxf(m.y, fpack(v.y, k));
            m.z = fmaxf(m.z, fpack(v.z, k));
            m.w = fmaxf(m.w, fpack(v.w, k));
        }
        int4 am;
        am.x = (int)(__float_as_uint(m.x) & 31u);
        am.y = (int)(__float_as_uint(m.y) & 31u);
        am.z = (int)(__float_as_uint(m.z) & 31u);
        am.w = (int)(__float_as_uint(m.w) & 31u);

        // Radix-ballot histogram: 10 ballots reconstruct all 21 class masks.
        // inter = popc(mg & mp): gt==k AND pred==k.
        #define SLOT(G, AM, VGT, SE) do {                                          \
            const int      _g  = (G);                                              \
            const int      _a  = (AM);                                             \
            const unsigned gb0 = __ballot_sync(0xffffffffu, (_g)      & 1);        \
            const unsigned gb1 = __ballot_sync(0xffffffffu, (_g >> 1) & 1);        \
            const unsigned gb2 = __ballot_sync(0xffffffffu, (_g >> 2) & 1);        \
            const unsigned gb3 = __ballot_sync(0xffffffffu, (_g >> 3) & 1);        \
            const unsigned gb4 = __ballot_sync(0xffffffffu, (_g >> 4) & 1);        \
            const unsigned ab0 = __ballot_sync(0xffffffffu, (_a)      & 1);        \
            const unsigned ab1 = __ballot_sync(0xffffffffu, (_a >> 1) & 1);        \
            const unsigned ab2 = __ballot_sync(0xffffffffu, (_a >> 2) & 1);        \
            const unsigned ab3 = __ballot_sync(0xffffffffu, (_a >> 3) & 1);        \
            const unsigned ab4 = __ballot_sync(0xffffffffu, (_a >> 4) & 1);        \
            const unsigned mg = (gb0^e0) & (gb1^e1) & (gb2^e2) & (gb3^e3) & (gb4^e4); \
            const unsigned mp = (ab0^e0) & (ab1^e1) & (ab2^e2) & (ab3^e3) & (ab4^e4); \
            acc += (unsigned)__popc(mg)                                            \
                 + ((unsigned)__popc(mg & mp) << 10)                               \
                 + ((unsigned)__popc(mp) << 20);                                   \
            atomicAdd(&s_T[wid][_g], (VGT) - __logf(SE));                          \
        } while (0)

        SLOT(g4.x, am.x, vgt.x, se.x);
        SLOT(g4.y, am.y, vgt.y, se.y);
        SLOT(g4.z, am.z, vgt.z, se.z);
        SLOT(g4.w, am.w, vgt.w, se.w);
        #undef SLOT
    }

    if (lane < NCLS) {
        c_At[wid][lane] = (float)( acc         & 1023u);
        c_I [wid][lane] = (float)((acc >> 10)  & 1023u);
        c_Ao[wid][lane] = (float)( acc >> 20);
    }
    __syncthreads();

    if (tid < NCLS) {
        float I = 0.f, At = 0.f, Ao = 0.f, T = 0.f;
        #pragma unroll
        for (int w = 0; w < 8; ++w) {
            I += c_I[w][tid]; At += c_At[w][tid]; Ao += c_Ao[w][tid]; T += s_T[w][tid];
        }
        atomicAdd(&g_I [b][tid], I);
        atomicAdd(&g_At[b][tid], At);
        atomicAdd(&g_Ao[b][tid], Ao);
        atomicAdd(&g_T [b][tid], T);
    }

    // Elect the last block to finalize.
    __threadfence();
    __syncthreads();
    if (tid == 0) {
        const unsigned r = atomicAdd(&g_done, 1u);
        s_last = (r == NBLK - 1u) ? 1 : 0;
    }
    __syncthreads();
    if (!s_last) return;
    __threadfence();   // acquire: all other blocks' g_* writes are visible

    // ---- finalize (runs in exactly one block) ----
    if (tid < NB * NCLS) {
        const int bb = tid / NCLS, k = tid % NCLS;
        const float I  = g_I [bb][k];
        const float At = g_At[bb][k];
        const float Ao = g_Ao[bb][k];
        const float T  = g_T [bb][k];
        // Restore the all-zero invariant for the next launch/replay.
        g_I [bb][k] = 0.f; g_At[bb][k] = 0.f; g_Ao[bb][k] = 0.f; g_T[bb][k] = 0.f;
        sh_d [bb][k] = 2.f * I / (Ao + At + EPS);  // union + inter == a_out + a_tgt
        sh_N [bb][k] = At;
        sh_Ts[bb][k] = T;
    }
    if (tid == 0) g_done = 0u;
    __syncthreads();

    float w = 0.f, wT = 0.f, wN = 0.f;
    if (tid < NCLS) {
        float dice = 0.f, N = 0.f, T = 0.f;
        #pragma unroll
        for (int bb = 0; bb < NB; ++bb) {
            dice += sh_d[bb][tid];
            N    += sh_N[bb][tid];
            T    += sh_Ts[bb][tid];
        }
        w  = 1.f - dice * 0.125f;   // weight[k]
        wT = w * T;
        wN = w * N;
    }
    if (tid < 32) {
        #pragma unroll
        for (int o = 16; o > 0; o >>= 1) {
            w  += __shfl_down_sync(0xffffffffu, w,  o);
            wT += __shfl_down_sync(0xffffffffu, wT, o);
            wN += __shfl_down_sync(0xffffffffu, wN, o);
        }
        if (tid == 0) out[0] = w * (1.f / 21.f) - wT / wN;  // mean(weight) + celoss
    }
}

extern "C" void kernel_launch(void* const* d_in, const int* in_sizes, int n_in,
                              void* d_out, int out_size) {
    const float* pr;
    const int*   gt;
    if (in_sizes[0] > in_sizes[1]) {
        pr = (const float*)d_in[0];
        gt = (const int*)  d_in[1];
    } else {
        pr = (const float*)d_in[1];
        gt = (const int*)  d_in[0];
    }
    float* out = (float*)d_out;

    fused_kernel<<<NBLK, TPB>>>(pr, gt, out);
}